// round 16
// baseline (speedup 1.0000x reference)
#include <cuda_runtime.h>
#include <cuda_bf16.h>

#define VOCAB  32000
#define NLABEL 16
#define NSTATE 64
#define BATCH  512
#define MAXLEN 512

typedef unsigned int       u32;
typedef unsigned long long ull;

// bf16x2 packed ops (sm_103a HFMA2.BF16_V2 / HADD2.BF16_V2).
#define HFMA2B(d, a, b, c) \
    asm("fma.rn.bf16x2 %0, %1, %2, %3;" : "=r"(d) : "r"(a), "r"(b), "r"(c))
#define HADD2B(d, a, b) \
    asm("add.rn.bf16x2 %0, %1, %2;" : "=r"(d) : "r"(a), "r"(b))

// Precomputed tables (device globals: no allocation allowed).
// g_Tbf16 layout (bf16 elements): element for (state r, K-index i) at
//   (i>>1)*128 + 2*r + (i&1)
// -> uint32 word w = jv*64 + r holds the bf16x2 K-pair (T[r][2jv], T[r][2jv+1]).
__device__ __align__(16) unsigned short g_Tbf16[NSTATE * NSTATE];
__device__ float g_Oexp[NLABEL * NSTATE];   // [l*64 + s] = softmax(output[l,:])[s]
__device__ float g_lse [VOCAB];             // logsumexp(emb[v,:])

// ---------------------------------------------------------------------------
// Fused prep: blocks [0,40) do row-softmax (2 rows/block: 64+16 rows total);
// blocks [40, 40+VOCAB/4) do per-vocab-row logsumexp (4 rows/block).
// ---------------------------------------------------------------------------
__global__ void prep_all_kernel(const float* __restrict__ transition,
                                const float* __restrict__ output,
                                const float* __restrict__ emb) {
    const int blk = blockIdx.x;
    if (blk < 40) {
        const int half = threadIdx.x >> 6;     // which row in this block
        const int i    = threadIdx.x & 63;     // state index within row
        const int r    = blk * 2 + half;       // global row 0..79
        const float* src = (r < NSTATE) ? (transition + r * NSTATE)
                                        : (output + (r - NSTATE) * NSTATE);
        float v = src[i];

        __shared__ float shm[4];
        __shared__ float shs[4];

        float m = v;
        #pragma unroll
        for (int d = 16; d; d >>= 1) m = fmaxf(m, __shfl_xor_sync(0xffffffffu, m, d));
        if ((threadIdx.x & 31) == 0) shm[threadIdx.x >> 5] = m;
        __syncthreads();
        m = fmaxf(shm[half * 2], shm[half * 2 + 1]);

        float e = expf(v - m);
        float s = e;
        #pragma unroll
        for (int d = 16; d; d >>= 1) s += __shfl_xor_sync(0xffffffffu, s, d);
        if ((threadIdx.x & 31) == 0) shs[threadIdx.x >> 5] = s;
        __syncthreads();
        s = shs[half * 2] + shs[half * 2 + 1];

        const float val = e / s;
        if (r < NSTATE) {
            const __nv_bfloat16 hv = __float2bfloat16(val);
            g_Tbf16[(i >> 1) * 128 + 2 * r + (i & 1)] =
                *reinterpret_cast<const unsigned short*>(&hv);
        } else {
            g_Oexp[(r - NSTATE) * NSTATE + i] = val;
        }
    } else {
        const int gw   = (blk - 40) * 4 + (threadIdx.x >> 5);
        const int lane = threadIdx.x & 31;
        if (gw >= VOCAB) return;
        const float* row = emb + gw * NSTATE;
        float s = expf(row[lane]) + expf(row[lane + 32]);
        #pragma unroll
        for (int d = 16; d; d >>= 1) s += __shfl_xor_sync(0xffffffffu, s, d);
        if (lane == 0) g_lse[gw] = logf(s);
    }
}

// ---------------------------------------------------------------------------
// Main: ONE WARP per batch element (R14 champion, 82.6us). Lane l owns
// states 2l, 2l+1; bf16x2 HFMA2 matvec; in-loop __syncwarp; dynamic
// double-buffer; renorm every 64 steps (flat if, proven). SINGLE delta vs
// R14: toks[] holds PRE-SHIFTED, PRE-CLAMPED prefetch offsets
// (toks[i] = sent[min(i+3, L-1)]) so the hot loop reads toks[t] with no
// per-step min/IMAD. No control-flow change whatsoever.
// ---------------------------------------------------------------------------
__global__ void __launch_bounds__(32) hmm_forward_kernel(
    const int*   __restrict__ sentences,
    const int*   __restrict__ length,
    const float* __restrict__ emb,
    float*       __restrict__ out)
{
    const int b    = blockIdx.x;
    const int lane = threadIdx.x;

    __shared__ __align__(16) u32 Gs[2][NSTATE / 2];   // bf16x2 words: (G[2l],G[2l+1])
    __shared__ int toks[MAXLEN];

    const int  L    = length[b];
    const int  Lm1  = L - 1;
    const int* sent = sentences + b * MAXLEN;

    // Stage PRE-SHIFTED prefetch tokens: toks[i] = sent[min(i+3, L-1)].
    for (int i = lane; i < L; i += 32) toks[i] = __ldg(&sent[min(i + 3, Lm1)]);

    // Transition rows for states s0=2*lane, s1=2*lane+1 as bf16x2 K-pairs.
    u32 TA[NSTATE / 2], TB[NSTATE / 2];
    {
        const uint2* Tp = reinterpret_cast<const uint2*>(g_Tbf16);
        #pragma unroll
        for (int jv = 0; jv < NSTATE / 2; ++jv) {
            const uint2 p = __ldg(&Tp[jv * 32 + lane]);   // words jv*64+2l, +1
            TA[jv] = p.x;
            TB[jv] = p.y;
        }
    }

    // ---- t = 0 ----
    const int tok0 = __ldg(&sent[0]);
    const float2 raw0 = *reinterpret_cast<const float2*>(&emb[tok0 * NSTATE + 2 * lane]);
    {
        const __nv_bfloat162 h0 = __floats2bfloat162_rn(__expf(raw0.x), __expf(raw0.y));
        Gs[0][lane] = *reinterpret_cast<const u32*>(&h0);
    }
    __syncwarp();   // Gs[0] + toks visible warp-wide

    // 3-deep emission-row prefetch (direct sent reads, clamped; prologue only).
    float2 r1 = *reinterpret_cast<const float2*>(&emb[__ldg(&sent[min(1, Lm1)]) * NSTATE + 2 * lane]);
    float2 r2 = *reinterpret_cast<const float2*>(&emb[__ldg(&sent[min(2, Lm1)]) * NSTATE + 2 * lane]);
    float2 r3 = *reinterpret_cast<const float2*>(&emb[__ldg(&sent[min(3, Lm1)]) * NSTATE + 2 * lane]);

    float off = 0.f;
    int   buf = 0;

    for (int t = 1; t < L; ++t) {
        float eA = __expf(r1.x);
        float eB = __expf(r1.y);
        r1 = r2; r2 = r3;
        r3 = *reinterpret_cast<const float2*>(&emb[toks[t] * NSTATE + 2 * lane]);

        if ((t & 63) == 0) {       // periodic renormalization (uniform branch)
            const float g0 = __uint_as_float(Gs[buf][0] << 16);   // bf16 lo -> fp32
            float c;
            asm("rcp.approx.f32 %0, %1;" : "=f"(c) : "f"(g0));
            eA *= c;
            eB *= c;
            off += __logf(g0);
        }

        // Two 64-wide matvecs in bf16x2: 8 LDS.128 + 64 HFMA2 (rt=2).
        // 4 accumulators per state bound bf16 accumulation roundoff.
        const uint4* Gv = reinterpret_cast<const uint4*>(Gs[buf]);
        u32 a0 = 0u, a1 = 0u, a2 = 0u, a3 = 0u;
        u32 b0 = 0u, b1 = 0u, b2 = 0u, b3 = 0u;
        #pragma unroll
        for (int q = 0; q < 8; ++q) {
            const uint4 g = Gv[q];
            HFMA2B(a0, TA[4 * q + 0], g.x, a0);
            HFMA2B(b0, TB[4 * q + 0], g.x, b0);
            HFMA2B(a1, TA[4 * q + 1], g.y, a1);
            HFMA2B(b1, TB[4 * q + 1], g.y, b1);
            HFMA2B(a2, TA[4 * q + 2], g.z, a2);
            HFMA2B(b2, TB[4 * q + 2], g.z, b2);
            HFMA2B(a3, TA[4 * q + 3], g.w, a3);
            HFMA2B(b3, TB[4 * q + 3], g.w, b3);
        }
        u32 sa, sb, u, v;
        HADD2B(u, a0, a1);
        HADD2B(v, a2, a3);
        HADD2B(sa, u, v);
        HADD2B(u, b0, b1);
        HADD2B(v, b2, b3);
        HADD2B(sb, u, v);
        // Horizontal pair-sum + emission multiply in fp32 (exact unpack).
        const float GnA = (__uint_as_float(sa << 16) +
                           __uint_as_float(sa & 0xffff0000u)) * eA;
        const float GnB = (__uint_as_float(sb << 16) +
                           __uint_as_float(sb & 0xffff0000u)) * eB;

        buf ^= 1;
        const __nv_bfloat162 hn = __floats2bfloat162_rn(GnA, GnB);
        Gs[buf][lane] = *reinterpret_cast<const u32*>(&hn);
        __syncwarp();
    }

    // ---- emission-normalizer sum S = sum_{t<L} lse[tok_t] ----
    // (toks is shifted, so read sentence tokens directly; off hot path.)
    float S = 0.f;
    for (int i = lane; i < L; i += 32) S += __ldg(&g_lse[__ldg(&sent[i])]);
    #pragma unroll
    for (int d = 16; d; d >>= 1) S += __shfl_xor_sync(0xffffffffu, S, d);

    // ---- readout: lanes 0..15 each compute one label (fp32) ----
    if (lane < NLABEL) {
        const float* O = g_Oexp + lane * NSTATE;
        const u32*  Gf = Gs[buf];
        float acc0 = 0.f, acc1 = 0.f;
        #pragma unroll
        for (int j = 0; j < NSTATE / 2; ++j) {
            const u32 wv = Gf[j];
            const float glo = __uint_as_float(wv << 16);
            const float ghi = __uint_as_float(wv & 0xffff0000u);
            acc0 = fmaf(__ldg(&O[2 * j + 0]), glo, acc0);
            acc1 = fmaf(__ldg(&O[2 * j + 1]), ghi, acc1);
        }
        out[b * NLABEL + lane] = __logf(acc0 + acc1) + off - S;
    }
}

// ---------------------------------------------------------------------------
extern "C" void kernel_launch(void* const* d_in, const int* in_sizes, int n_in,
                              void* d_out, int out_size) {
    const int*   sentences  = nullptr;
    const int*   length     = nullptr;
    const float* emb        = nullptr;
    const float* transition = nullptr;
    const float* output     = nullptr;

    for (int i = 0; i < n_in; ++i) {
        switch (in_sizes[i]) {
            case BATCH * MAXLEN:   sentences  = (const int*)  d_in[i]; break;
            case BATCH:            length     = (const int*)  d_in[i]; break;
            case VOCAB * NSTATE:   emb        = (const float*)d_in[i]; break;
            case NSTATE * NSTATE:  transition = (const float*)d_in[i]; break;
            case NLABEL * NSTATE:  output     = (const float*)d_in[i]; break;
            default: break;
        }
    }

    prep_all_kernel<<<40 + VOCAB / 4, 128>>>(transition, output, emb);
    hmm_forward_kernel<<<BATCH, 32>>>(sentences, length, emb, (float*)d_out);
}

// round 17
// speedup vs baseline: 1.7578x; 1.7578x over previous
#include <cuda_runtime.h>
#include <cuda_bf16.h>

#define VOCAB  32000
#define NLABEL 16
#define NSTATE 64
#define BATCH  512
#define MAXLEN 512

typedef unsigned int       u32;
typedef unsigned long long ull;

// bf16x2 packed ops (sm_103a HFMA2.BF16_V2 / HADD2.BF16_V2).
#define HFMA2B(d, a, b, c) \
    asm("fma.rn.bf16x2 %0, %1, %2, %3;" : "=r"(d) : "r"(a), "r"(b), "r"(c))
#define HADD2B(d, a, b) \
    asm("add.rn.bf16x2 %0, %1, %2;" : "=r"(d) : "r"(a), "r"(b))

// Precomputed tables (device globals: no allocation allowed).
// g_Tbf16 layout (bf16 elements): element for (state r, K-index i) at
//   (i>>1)*128 + 2*r + (i&1)
// -> uint32 word w = jv*64 + r holds the bf16x2 K-pair (T[r][2jv], T[r][2jv+1]).
__device__ __align__(16) unsigned short g_Tbf16[NSTATE * NSTATE];
__device__ float g_Oexp[NLABEL * NSTATE];   // [l*64 + s] = softmax(output[l,:])[s]
__device__ float g_lse [VOCAB];             // logsumexp(emb[v,:])

// ---------------------------------------------------------------------------
// Fused prep: blocks [0,40) do row-softmax (2 rows/block: 64+16 rows total);
// blocks [40, 40+VOCAB/4) do per-vocab-row logsumexp (4 rows/block).
// ---------------------------------------------------------------------------
__global__ void prep_all_kernel(const float* __restrict__ transition,
                                const float* __restrict__ output,
                                const float* __restrict__ emb) {
    const int blk = blockIdx.x;
    if (blk < 40) {
        const int half = threadIdx.x >> 6;     // which row in this block
        const int i    = threadIdx.x & 63;     // state index within row
        const int r    = blk * 2 + half;       // global row 0..79
        const float* src = (r < NSTATE) ? (transition + r * NSTATE)
                                        : (output + (r - NSTATE) * NSTATE);
        float v = src[i];

        __shared__ float shm[4];
        __shared__ float shs[4];

        float m = v;
        #pragma unroll
        for (int d = 16; d; d >>= 1) m = fmaxf(m, __shfl_xor_sync(0xffffffffu, m, d));
        if ((threadIdx.x & 31) == 0) shm[threadIdx.x >> 5] = m;
        __syncthreads();
        m = fmaxf(shm[half * 2], shm[half * 2 + 1]);

        float e = expf(v - m);
        float s = e;
        #pragma unroll
        for (int d = 16; d; d >>= 1) s += __shfl_xor_sync(0xffffffffu, s, d);
        if ((threadIdx.x & 31) == 0) shs[threadIdx.x >> 5] = s;
        __syncthreads();
        s = shs[half * 2] + shs[half * 2 + 1];

        const float val = e / s;
        if (r < NSTATE) {
            const __nv_bfloat16 hv = __float2bfloat16(val);
            g_Tbf16[(i >> 1) * 128 + 2 * r + (i & 1)] =
                *reinterpret_cast<const unsigned short*>(&hv);
        } else {
            g_Oexp[(r - NSTATE) * NSTATE + i] = val;
        }
    } else {
        const int gw   = (blk - 40) * 4 + (threadIdx.x >> 5);
        const int lane = threadIdx.x & 31;
        if (gw >= VOCAB) return;
        const float* row = emb + gw * NSTATE;
        float s = expf(row[lane]) + expf(row[lane + 32]);
        #pragma unroll
        for (int d = 16; d; d >>= 1) s += __shfl_xor_sync(0xffffffffu, s, d);
        if (lane == 0) g_lse[gw] = logf(s);
    }
}

// ---------------------------------------------------------------------------
// Main: ONE WARP per batch element (champion skeleton). Lane l owns states
// 2l, 2l+1. Matvec in bf16x2 HFMA2 (rt=2 vs FFMA2's rt=3): T rows and the G
// exchange are bf16; emission factor, renorm, horizontal sums, and output
// stay fp32 (bf16->fp32 unpack is exact). 4 bf16x2 accumulators per state
// bound accumulation roundoff. Everything else is byte-identical in spirit
// to the 96.7us champion: in-loop __syncwarp, dynamic double-buffer index,
// exp at loop top, 3-deep emission prefetch, renorm every 64 steps.
// ---------------------------------------------------------------------------
__global__ void __launch_bounds__(32) hmm_forward_kernel(
    const int*   __restrict__ sentences,
    const int*   __restrict__ length,
    const float* __restrict__ emb,
    float*       __restrict__ out)
{
    const int b    = blockIdx.x;
    const int lane = threadIdx.x;

    __shared__ __align__(16) u32 Gs[2][NSTATE / 2];   // bf16x2 words: (G[2l],G[2l+1])
    __shared__ int toks[MAXLEN];

    const int  L    = length[b];
    const int  Lm1  = L - 1;
    const int* sent = sentences + b * MAXLEN;

    // Stage tokens in SMEM (coalesced, 16 iterations max).
    for (int i = lane; i < L; i += 32) toks[i] = __ldg(&sent[i]);

    // Transition rows for states s0=2*lane, s1=2*lane+1 as bf16x2 K-pairs:
    // TA[jv] = (T[s0][2jv], T[s0][2jv+1]), TB likewise. LDG.64 coalesced.
    u32 TA[NSTATE / 2], TB[NSTATE / 2];
    {
        const uint2* Tp = reinterpret_cast<const uint2*>(g_Tbf16);
        #pragma unroll
        for (int jv = 0; jv < NSTATE / 2; ++jv) {
            const uint2 p = __ldg(&Tp[jv * 32 + lane]);   // words jv*64+2l, +1
            TA[jv] = p.x;
            TB[jv] = p.y;
        }
    }

    // ---- t = 0 ----
    const int tok0 = __ldg(&sent[0]);
    const float2 raw0 = *reinterpret_cast<const float2*>(&emb[tok0 * NSTATE + 2 * lane]);
    {
        const __nv_bfloat162 h0 = __floats2bfloat162_rn(__expf(raw0.x), __expf(raw0.y));
        Gs[0][lane] = *reinterpret_cast<const u32*>(&h0);
    }
    __syncwarp();   // Gs[0] + toks visible warp-wide

    // 3-deep emission-row prefetch (clamped indices: always valid loads).
    float2 r1 = *reinterpret_cast<const float2*>(&emb[toks[min(1, Lm1)] * NSTATE + 2 * lane]);
    float2 r2 = *reinterpret_cast<const float2*>(&emb[toks[min(2, Lm1)] * NSTATE + 2 * lane]);
    float2 r3 = *reinterpret_cast<const float2*>(&emb[toks[min(3, Lm1)] * NSTATE + 2 * lane]);

    float off = 0.f;
    int   buf = 0;

    for (int t = 1; t < L; ++t) {
        float eA = __expf(r1.x);
        float eB = __expf(r1.y);
        r1 = r2; r2 = r3;
        r3 = *reinterpret_cast<const float2*>(&emb[toks[min(t + 3, Lm1)] * NSTATE + 2 * lane]);

        if ((t & 63) == 0) {       // periodic renormalization (uniform branch)
            const float g0 = __uint_as_float(Gs[buf][0] << 16);   // bf16 lo -> fp32
            float c;
            asm("rcp.approx.f32 %0, %1;" : "=f"(c) : "f"(g0));
            eA *= c;
            eB *= c;
            off += __logf(g0);
        }

        // Two 64-wide matvecs in bf16x2: 8 LDS.128 + 64 HFMA2 (rt=2).
        // 4 accumulators per state bound bf16 accumulation roundoff.
        const uint4* Gv = reinterpret_cast<const uint4*>(Gs[buf]);
        u32 a0 = 0u, a1 = 0u, a2 = 0u, a3 = 0u;
        u32 b0 = 0u, b1 = 0u, b2 = 0u, b3 = 0u;
        #pragma unroll
        for (int q = 0; q < 8; ++q) {
            const uint4 g = Gv[q];
            HFMA2B(a0, TA[4 * q + 0], g.x, a0);
            HFMA2B(b0, TB[4 * q + 0], g.x, b0);
            HFMA2B(a1, TA[4 * q + 1], g.y, a1);
            HFMA2B(b1, TB[4 * q + 1], g.y, b1);
            HFMA2B(a2, TA[4 * q + 2], g.z, a2);
            HFMA2B(b2, TB[4 * q + 2], g.z, b2);
            HFMA2B(a3, TA[4 * q + 3], g.w, a3);
            HFMA2B(b3, TB[4 * q + 3], g.w, b3);
        }
        u32 sa, sb, u, v;
        HADD2B(u, a0, a1);
        HADD2B(v, a2, a3);
        HADD2B(sa, u, v);
        HADD2B(u, b0, b1);
        HADD2B(v, b2, b3);
        HADD2B(sb, u, v);
        // Horizontal pair-sum + emission multiply in fp32 (exact unpack).
        const float GnA = (__uint_as_float(sa << 16) +
                           __uint_as_float(sa & 0xffff0000u)) * eA;
        const float GnB = (__uint_as_float(sb << 16) +
                           __uint_as_float(sb & 0xffff0000u)) * eB;

        buf ^= 1;
        const __nv_bfloat162 hn = __floats2bfloat162_rn(GnA, GnB);
        Gs[buf][lane] = *reinterpret_cast<const u32*>(&hn);
        __syncwarp();
    }

    // ---- emission-normalizer sum S = sum_{t<L} lse[tok_t] ----
    float S = 0.f;
    for (int i = lane; i < L; i += 32) S += __ldg(&g_lse[toks[i]]);
    #pragma unroll
    for (int d = 16; d; d >>= 1) S += __shfl_xor_sync(0xffffffffu, S, d);

    // ---- readout: lanes 0..15 each compute one label (fp32) ----
    if (lane < NLABEL) {
        const float* O = g_Oexp + lane * NSTATE;
        const u32*  Gf = Gs[buf];
        float acc0 = 0.f, acc1 = 0.f;
        #pragma unroll
        for (int j = 0; j < NSTATE / 2; ++j) {
            const u32 wv = Gf[j];
            const float glo = __uint_as_float(wv << 16);
            const float ghi = __uint_as_float(wv & 0xffff0000u);
            acc0 = fmaf(__ldg(&O[2 * j + 0]), glo, acc0);
            acc1 = fmaf(__ldg(&O[2 * j + 1]), ghi, acc1);
        }
        out[b * NLABEL + lane] = __logf(acc0 + acc1) + off - S;
    }
}

// ---------------------------------------------------------------------------
extern "C" void kernel_launch(void* const* d_in, const int* in_sizes, int n_in,
                              void* d_out, int out_size) {
    const int*   sentences  = nullptr;
    const int*   length     = nullptr;
    const float* emb        = nullptr;
    const float* transition = nullptr;
    const float* output     = nullptr;

    for (int i = 0; i < n_in; ++i) {
        switch (in_sizes[i]) {
            case BATCH * MAXLEN:   sentences  = (const int*)  d_in[i]; break;
            case BATCH:            length     = (const int*)  d_in[i]; break;
            case VOCAB * NSTATE:   emb        = (const float*)d_in[i]; break;
            case NSTATE * NSTATE:  transition = (const float*)d_in[i]; break;
            case NLABEL * NSTATE:  output     = (const float*)d_in[i]; break;
            default: break;
        }
    }

    prep_all_kernel<<<40 + VOCAB / 4, 128>>>(transition, output, emb);
    hmm_forward_kernel<<<BATCH, 32>>>(sentences, length, emb, (float*)d_out);
}